// round 3
// baseline (speedup 1.0000x reference)
#include <cuda_runtime.h>
#include <math.h>

#define N 8192
#define D 1024

// Scratch (allocation-free rule: __device__ globals)
__device__ float g_a[N];        // sigmoid(x @ w)
__device__ float g_m[N];        // main weight (reference writes at row idx)
__device__ float g_c[N];        // cross weight (reference writes at row idx-1)
__device__ int   g_idx[N];      // floor(b) per column, non-decreasing

// ---------------------------------------------------------------------------
// Kernel 1: z = x @ w, a = sigmoid(z).  One warp per row (R1 config, bitwise
// identical accumulation order -> g_a unchanged).
// ---------------------------------------------------------------------------
__global__ void k_logits(const float* __restrict__ x, const float* __restrict__ w) {
    const int warp = threadIdx.x >> 5;
    const int lane = threadIdx.x & 31;
    const int row  = blockIdx.x * 8 + warp;

    const float4* xr = reinterpret_cast<const float4*>(x) + (size_t)row * (D / 4);
    const float4* w4 = reinterpret_cast<const float4*>(w);

    float s = 0.f;
#pragma unroll
    for (int k = 0; k < D / 128; k++) {           // 8 iterations
        float4 xv = xr[lane + 32 * k];
        float4 wv = __ldg(&w4[lane + 32 * k]);
        s += xv.x * wv.x;
        s += xv.y * wv.y;
        s += xv.z * wv.z;
        s += xv.w * wv.w;
    }
#pragma unroll
    for (int off = 16; off; off >>= 1)
        s += __shfl_xor_sync(0xffffffffu, s, off);

    if (lane == 0) {
        float z = s, a;
        if (z >= 0.f) {
            a = 1.f / (1.f + expf(-z));
        } else {
            float e = expf(z);
            a = e / (1.f + e);
        }
        g_a[row] = a;
    }
}

// ---------------------------------------------------------------------------
// Kernel 2: b = cumsum(a) replicating jax.lax.associative_scan's fp32 tree,
// then derive per-column idx / main / cross. No g_b array, no atomics.
// Tree levels 1..13 live in shared; levels with n<=32 run in warp 0 only.
// ---------------------------------------------------------------------------
__global__ void k_scan() {
    __shared__ float sh[8192];
    const int tid = threadIdx.x;   // 1024 threads
    // off(l) = 8192 - 2*(8192 >> l), levels 1..13

    // up-sweep: level 1 from global a
    for (int i = tid; i < 4096; i += 1024)
        sh[i] = g_a[2 * i] + g_a[2 * i + 1];
    __syncthreads();
    // block levels 2..7 (n = 2048 .. 64)
    for (int l = 2; l <= 7; l++) {
        const int n    = N >> l;
        const int off  = 8192 - 2 * (8192 >> l);
        const int offp = 8192 - 2 * (8192 >> (l - 1));
        for (int i = tid; i < n; i += 1024)
            sh[off + i] = sh[offp + 2 * i] + sh[offp + 2 * i + 1];
        __syncthreads();
    }

    // warp 0: up levels 8..13 (n = 32..1), then down levels 12..8 (n=2..32)
    if (tid < 32) {
        for (int l = 8; l <= 13; l++) {
            const int n    = N >> l;
            const int off  = 8192 - 2 * (8192 >> l);
            const int offp = 8192 - 2 * (8192 >> (l - 1));
            if (tid < n)
                sh[off + tid] = sh[offp + 2 * tid] + sh[offp + 2 * tid + 1];
            __syncwarp();
        }
        // level 13 scan == itself. down-sweep 12..8 in place.
        for (int l = 12; l >= 8; l--) {
            const int n    = N >> l;
            const int off  = 8192 - 2 * (8192 >> l);
            const int offc = 8192 - 2 * (8192 >> (l + 1));
            float v = 0.f;
            if (tid < n) {
                if (tid & 1)       v = sh[offc + (tid >> 1)];
                else if (tid == 0) v = sh[off];
                else               v = sh[offc + (tid >> 1) - 1] + sh[off + tid];
            }
            __syncwarp();
            if (tid < n) sh[off + tid] = v;
            __syncwarp();
        }
    }
    __syncthreads();

    // block down levels 7..1 (n = 64 .. 4096), in place per level
    for (int l = 7; l >= 1; l--) {
        const int n    = N >> l;
        const int off  = 8192 - 2 * (8192 >> l);
        const int offc = 8192 - 2 * (8192 >> (l + 1));
        for (int i = tid; i < n; i += 1024) {
            float v;
            if (i & 1)       v = sh[offc + (i >> 1)];
            else if (i == 0) v = sh[off];
            else             v = sh[offc + (i >> 1) - 1] + sh[off + i];
            sh[off + i] = v;
        }
        __syncthreads();
    }

    // level-0 values on the fly:  b(k) = k==0 ? a[0] : (k odd ? sh[k>>1]
    //                                   : sh[(k>>1)-1] + a[k])
    for (int i = tid; i < N; i += 1024) {
        const float ai = g_a[i];
        float bi;
        if (i == 0)      bi = ai;
        else if (i & 1)  bi = sh[i >> 1];
        else             bi = sh[(i >> 1) - 1] + ai;

        int prev;
        if (i == 0) {
            prev = 0;
        } else {
            const int k = i - 1;
            float bp;
            if (k == 0)      bp = g_a[0];
            else if (k & 1)  bp = sh[k >> 1];
            else             bp = sh[(k >> 1) - 1] + g_a[k];
            prev = (int)floorf(bp);
        }
        const int idx   = (int)floorf(bi);
        const bool same = (idx == prev);
        const float frac = bi - (float)idx;

        g_m[i]   = same ? ai : frac;
        g_c[i]   = same ? 0.f : (ai - frac);
        g_idx[i] = idx;
    }
}

// ---------------------------------------------------------------------------
// Kernel 3: gather. One block per output row j. Span found by binary search
// on the non-decreasing g_idx: columns with idx in {j, j+1}.
// ---------------------------------------------------------------------------
__global__ void k_gather(const float* __restrict__ x, float* __restrict__ out) {
    const int j = blockIdx.x;     // output row
    const int t = threadIdx.x;    // 0..255, float4 lanes

    // lower_bound(idx >= j) and lower_bound(idx >= j+2); done redundantly in
    // every thread (g_idx is L1-broadcast-friendly).
    int lo = 0, hi = N;
    while (lo < hi) {
        int mid = (lo + hi) >> 1;
        if (__ldg(&g_idx[mid]) < j) lo = mid + 1; else hi = mid;
    }
    const int s = lo;
    hi = N;
    while (lo < hi) {
        int mid = (lo + hi) >> 1;
        if (__ldg(&g_idx[mid]) < j + 2) lo = mid + 1; else hi = mid;
    }
    const int e = lo;

    float4 acc = make_float4(0.f, 0.f, 0.f, 0.f);
    for (int i = s; i < e; i++) {
        const int idx = __ldg(&g_idx[i]);
        float wgt = 0.f;
        if (idx == j)          wgt = __ldg(&g_m[i]);
        else if (idx == j + 1) wgt = __ldg(&g_c[i]);
        if (wgt != 0.f) {       // warp-uniform; zero weight contributes zero
            const float4 v = reinterpret_cast<const float4*>(x)[(size_t)i * (D / 4) + t];
            acc.x += wgt * v.x;
            acc.y += wgt * v.y;
            acc.z += wgt * v.z;
            acc.w += wgt * v.w;
        }
    }
    reinterpret_cast<float4*>(out)[(size_t)j * (D / 4) + t] = acc;
}

// ---------------------------------------------------------------------------
extern "C" void kernel_launch(void* const* d_in, const int* in_sizes, int n_in,
                              void* d_out, int out_size) {
    const float* x = (const float*)d_in[0];   // [8192, 1024] f32
    const float* w = (const float*)d_in[1];   // [1024, 1]    f32
    float* out = (float*)d_out;               // [8192, 1024] f32

    k_logits<<<N / 8, 256>>>(x, w);
    k_scan<<<1, 1024>>>();
    k_gather<<<N, 256>>>(x, out);
}

// round 4
// speedup vs baseline: 1.4409x; 1.4409x over previous
#include <cuda_runtime.h>
#include <math.h>

#define N 8192
#define D 1024

// Scratch (allocation-free rule: __device__ globals)
__device__ float g_a[N];            // sigmoid(x @ w)
__device__ int4  g_pack[N];         // {idx, bits(m), bits(c), 0} per column
__device__ int   g_rowstart[N + 2]; // lower_bound(idx >= j), j in [0, N+1]

// ---------------------------------------------------------------------------
// Kernel 1: z = x @ w, a = sigmoid(z).  One warp per row (validated config;
// accumulation order bitwise identical to R1 -> g_a unchanged).
// ---------------------------------------------------------------------------
__global__ void k_logits(const float* __restrict__ x, const float* __restrict__ w) {
    const int warp = threadIdx.x >> 5;
    const int lane = threadIdx.x & 31;
    const int row  = blockIdx.x * 8 + warp;

    const float4* xr = reinterpret_cast<const float4*>(x) + (size_t)row * (D / 4);
    const float4* w4 = reinterpret_cast<const float4*>(w);

    float s = 0.f;
#pragma unroll
    for (int k = 0; k < D / 128; k++) {           // 8 iterations
        float4 xv = xr[lane + 32 * k];
        float4 wv = __ldg(&w4[lane + 32 * k]);
        s += xv.x * wv.x;
        s += xv.y * wv.y;
        s += xv.z * wv.z;
        s += xv.w * wv.w;
    }
#pragma unroll
    for (int off = 16; off; off >>= 1)
        s += __shfl_xor_sync(0xffffffffu, s, off);

    if (lane == 0) {
        float z = s, a;
        if (z >= 0.f) {
            a = 1.f / (1.f + expf(-z));
        } else {
            float e = expf(z);
            a = e / (1.f + e);
        }
        g_a[row] = a;
    }
}

// ---------------------------------------------------------------------------
// Kernel 2: b = cumsum(a) replicating jax.lax.associative_scan's fp32 tree,
// then derive per-column {idx, m, c} and the exact rowstart table.
// idx is non-decreasing with steps <= 1 (a_i < 1), so rowstart needs no
// atomics and no search: the crossing thread writes it directly.
// ---------------------------------------------------------------------------
__global__ void k_scan() {
    __shared__ float sh[8192];
    const int tid = threadIdx.x;   // 1024 threads
    // off(l) = 8192 - 2*(8192 >> l), levels 1..13

    // up-sweep: level 1 from global a
    for (int i = tid; i < 4096; i += 1024)
        sh[i] = g_a[2 * i] + g_a[2 * i + 1];
    __syncthreads();
    for (int l = 2; l <= 7; l++) {                 // n = 2048 .. 64
        const int n    = N >> l;
        const int off  = 8192 - 2 * (8192 >> l);
        const int offp = 8192 - 2 * (8192 >> (l - 1));
        for (int i = tid; i < n; i += 1024)
            sh[off + i] = sh[offp + 2 * i] + sh[offp + 2 * i + 1];
        __syncthreads();
    }

    // warp 0: up levels 8..13 (n = 32..1), then down levels 12..8 (n = 2..32)
    if (tid < 32) {
        for (int l = 8; l <= 13; l++) {
            const int n    = N >> l;
            const int off  = 8192 - 2 * (8192 >> l);
            const int offp = 8192 - 2 * (8192 >> (l - 1));
            if (tid < n)
                sh[off + tid] = sh[offp + 2 * tid] + sh[offp + 2 * tid + 1];
            __syncwarp();
        }
        for (int l = 12; l >= 8; l--) {
            const int n    = N >> l;
            const int off  = 8192 - 2 * (8192 >> l);
            const int offc = 8192 - 2 * (8192 >> (l + 1));
            float v = 0.f;
            if (tid < n) {
                if (tid & 1)       v = sh[offc + (tid >> 1)];
                else if (tid == 0) v = sh[off];
                else               v = sh[offc + (tid >> 1) - 1] + sh[off + tid];
            }
            __syncwarp();
            if (tid < n) sh[off + tid] = v;
            __syncwarp();
        }
    }
    __syncthreads();

    for (int l = 7; l >= 1; l--) {                 // n = 64 .. 4096, in place
        const int n    = N >> l;
        const int off  = 8192 - 2 * (8192 >> l);
        const int offc = 8192 - 2 * (8192 >> (l + 1));
        for (int i = tid; i < n; i += 1024) {
            float v;
            if (i & 1)       v = sh[offc + (i >> 1)];
            else if (i == 0) v = sh[off];
            else             v = sh[offc + (i >> 1) - 1] + sh[off + i];
            sh[off + i] = v;
        }
        __syncthreads();
    }

    // level-0 b on the fly, derive weights + rowstart.
    int last_idx = 0;   // value of idx[N-1] seen by the thread owning i=N-1
    for (int i = tid; i < N; i += 1024) {
        const float ai = g_a[i];
        float bi;
        if (i == 0)      bi = ai;
        else if (i & 1)  bi = sh[i >> 1];
        else             bi = sh[(i >> 1) - 1] + ai;

        int prev;
        if (i == 0) {
            prev = 0;
        } else {
            const int k = i - 1;
            float bp;
            if (k == 0)      bp = g_a[0];
            else if (k & 1)  bp = sh[k >> 1];
            else             bp = sh[(k >> 1) - 1] + g_a[k];
            prev = (int)floorf(bp);
        }
        const int idx   = (int)floorf(bi);
        const bool same = (idx == prev);
        const float frac = bi - (float)idx;

        const float m = same ? ai : frac;
        const float c = same ? 0.f : (ai - frac);
        g_pack[i] = make_int4(idx, __float_as_int(m), __float_as_int(c), 0);

        // rowstart: steps of idx are 0 or +1, no skips.
        if (i == 0) g_rowstart[0] = 0;
        else if (!same) g_rowstart[idx] = i;   // idx == prev+1 here
        if (i == N - 1) last_idx = idx;
    }
    __syncthreads();

    // broadcast idx[N-1] via shared, then tail-fill rowstart[j] = N
    __shared__ int s_last;
    if (tid == ((N - 1) & 1023)) s_last = last_idx;
    __syncthreads();
    const int tail0 = s_last + 1;
    for (int j = tail0 + tid; j <= N + 1; j += 1024)
        g_rowstart[j] = N;
}

// ---------------------------------------------------------------------------
// Kernel 3: gather. One block per output row j. Span = [rowstart[j],
// rowstart[j+2]): exactly the columns with idx in {j, j+1}. Two independent
// L2 loads replace the binary search. Empty rows write zeros.
// ---------------------------------------------------------------------------
__global__ void k_gather(const float* __restrict__ x, float* __restrict__ out) {
    const int j = blockIdx.x;     // output row
    const int t = threadIdx.x;    // 0..255, float4 lanes

    const int s = __ldg(&g_rowstart[j]);
    const int e = __ldg(&g_rowstart[j + 2]);

    float4 acc = make_float4(0.f, 0.f, 0.f, 0.f);
    for (int i = s; i < e; i++) {
        const int4 p  = __ldg(&g_pack[i]);
        const int idx = p.x;
        float wgt = 0.f;
        if (idx == j)          wgt = __int_as_float(p.y);   // m
        else if (idx == j + 1) wgt = __int_as_float(p.z);   // c
        if (wgt != 0.f) {       // warp-uniform; zero weight contributes zero
            const float4 v = reinterpret_cast<const float4*>(x)[(size_t)i * (D / 4) + t];
            acc.x += wgt * v.x;
            acc.y += wgt * v.y;
            acc.z += wgt * v.z;
            acc.w += wgt * v.w;
        }
    }
    reinterpret_cast<float4*>(out)[(size_t)j * (D / 4) + t] = acc;
}

// ---------------------------------------------------------------------------
extern "C" void kernel_launch(void* const* d_in, const int* in_sizes, int n_in,
                              void* d_out, int out_size) {
    const float* x = (const float*)d_in[0];   // [8192, 1024] f32
    const float* w = (const float*)d_in[1];   // [1024, 1]    f32
    float* out = (float*)d_out;               // [8192, 1024] f32

    k_logits<<<N / 8, 256>>>(x, w);
    k_scan<<<1, 1024>>>();
    k_gather<<<N, 256>>>(x, out);
}

// round 5
// speedup vs baseline: 1.4545x; 1.0094x over previous
#include <cuda_runtime.h>
#include <math.h>

#define N 8192
#define D 1024

// Scratch (allocation-free rule: __device__ globals)
__device__ float g_a[N];            // sigmoid(x @ w)
__device__ int4  g_pack[N];         // {idx, bits(m), bits(c), 0} per column
__device__ int   g_rowstart[N + 2]; // lower_bound(idx >= j), j in [0, N+1]

__device__ __forceinline__ unsigned smem_u32(const void* p) {
    unsigned r;
    asm("{ .reg .u64 t; cvta.to.shared.u64 t, %1; cvt.u32.u64 %0, t; }"
        : "=r"(r) : "l"(p));
    return r;
}

__device__ __forceinline__ void mbar_wait(unsigned mbar, unsigned parity) {
    asm volatile(
        "{\n\t"
        ".reg .pred P;\n\t"
        "WL_%=: mbarrier.try_wait.parity.shared.b64 P, [%0], %1, 0x989680;\n\t"
        "@P bra.uni WD_%=;\n\t"
        "bra.uni WL_%=;\n\t"
        "WD_%=:\n\t"
        "}" :: "r"(mbar), "r"(parity) : "memory");
}

// ---------------------------------------------------------------------------
// Kernel 1: z = x @ w, a = sigmoid(z).  One 32KB bulk-copy (8 rows) per block
// into shared, then one warp per row computes the dot with the SAME FFMA
// order on the SAME values as the validated kernel -> g_a bitwise unchanged.
// ---------------------------------------------------------------------------
__global__ void __launch_bounds__(256) k_logits(const float* __restrict__ x,
                                                const float* __restrict__ w) {
    __shared__ alignas(128) float sx[8 * D];       // 32 KB
    __shared__ alignas(8) unsigned long long mbar;

    const int tid  = threadIdx.x;
    const int warp = tid >> 5;
    const int lane = tid & 31;

    const unsigned mb = smem_u32(&mbar);
    if (tid == 0) {
        asm volatile("mbarrier.init.shared.b64 [%0], 1;" :: "r"(mb) : "memory");
    }
    __syncthreads();
    if (tid == 0) {
        asm volatile("mbarrier.arrive.expect_tx.shared.b64 _, [%0], %1;"
                     :: "r"(mb), "r"(32768u) : "memory");
        const float* src = x + (size_t)blockIdx.x * 8 * D;
        asm volatile(
            "cp.async.bulk.shared::cta.global.mbarrier::complete_tx::bytes"
            " [%0], [%1], %2, [%3];"
            :: "r"(smem_u32(sx)), "l"(src), "r"(32768u), "r"(mb) : "memory");
    }
    mbar_wait(mb, 0);

    const float4* xr = reinterpret_cast<const float4*>(sx) + warp * (D / 4);
    const float4* w4 = reinterpret_cast<const float4*>(w);

    float s = 0.f;
#pragma unroll
    for (int k = 0; k < D / 128; k++) {            // 8 iterations
        float4 xv = xr[lane + 32 * k];
        float4 wv = __ldg(&w4[lane + 32 * k]);
        s += xv.x * wv.x;
        s += xv.y * wv.y;
        s += xv.z * wv.z;
        s += xv.w * wv.w;
    }
#pragma unroll
    for (int off = 16; off; off >>= 1)
        s += __shfl_xor_sync(0xffffffffu, s, off);

    if (lane == 0) {
        float z = s, a;
        if (z >= 0.f) {
            a = 1.f / (1.f + expf(-z));
        } else {
            float e = expf(z);
            a = e / (1.f + e);
        }
        g_a[blockIdx.x * 8 + warp] = a;
    }
}

// ---------------------------------------------------------------------------
// Kernel 2: b = cumsum(a) replicating jax.lax.associative_scan's fp32 tree,
// then derive per-column {idx, m, c} and the exact rowstart table.
// idx is non-decreasing with steps <= 1 (a_i < 1): crossing thread writes
// rowstart directly, no atomics, no search.
// ---------------------------------------------------------------------------
__global__ void k_scan() {
    __shared__ float sh[8192];
    const int tid = threadIdx.x;   // 1024 threads

    for (int i = tid; i < 4096; i += 1024)
        sh[i] = g_a[2 * i] + g_a[2 * i + 1];
    __syncthreads();
    for (int l = 2; l <= 7; l++) {                 // n = 2048 .. 64
        const int n    = N >> l;
        const int off  = 8192 - 2 * (8192 >> l);
        const int offp = 8192 - 2 * (8192 >> (l - 1));
        for (int i = tid; i < n; i += 1024)
            sh[off + i] = sh[offp + 2 * i] + sh[offp + 2 * i + 1];
        __syncthreads();
    }

    if (tid < 32) {
        for (int l = 8; l <= 13; l++) {
            const int n    = N >> l;
            const int off  = 8192 - 2 * (8192 >> l);
            const int offp = 8192 - 2 * (8192 >> (l - 1));
            if (tid < n)
                sh[off + tid] = sh[offp + 2 * tid] + sh[offp + 2 * tid + 1];
            __syncwarp();
        }
        for (int l = 12; l >= 8; l--) {
            const int n    = N >> l;
            const int off  = 8192 - 2 * (8192 >> l);
            const int offc = 8192 - 2 * (8192 >> (l + 1));
            float v = 0.f;
            if (tid < n) {
                if (tid & 1)       v = sh[offc + (tid >> 1)];
                else if (tid == 0) v = sh[off];
                else               v = sh[offc + (tid >> 1) - 1] + sh[off + tid];
            }
            __syncwarp();
            if (tid < n) sh[off + tid] = v;
            __syncwarp();
        }
    }
    __syncthreads();

    for (int l = 7; l >= 1; l--) {                 // n = 64 .. 4096, in place
        const int n    = N >> l;
        const int off  = 8192 - 2 * (8192 >> l);
        const int offc = 8192 - 2 * (8192 >> (l + 1));
        for (int i = tid; i < n; i += 1024) {
            float v;
            if (i & 1)       v = sh[offc + (i >> 1)];
            else if (i == 0) v = sh[off];
            else             v = sh[offc + (i >> 1) - 1] + sh[off + i];
            sh[off + i] = v;
        }
        __syncthreads();
    }

    int last_idx = 0;
    for (int i = tid; i < N; i += 1024) {
        const float ai = g_a[i];
        float bi;
        if (i == 0)      bi = ai;
        else if (i & 1)  bi = sh[i >> 1];
        else             bi = sh[(i >> 1) - 1] + ai;

        int prev;
        if (i == 0) {
            prev = 0;
        } else {
            const int k = i - 1;
            float bp;
            if (k == 0)      bp = g_a[0];
            else if (k & 1)  bp = sh[k >> 1];
            else             bp = sh[(k >> 1) - 1] + g_a[k];
            prev = (int)floorf(bp);
        }
        const int idx   = (int)floorf(bi);
        const bool same = (idx == prev);
        const float frac = bi - (float)idx;

        const float m = same ? ai : frac;
        const float c = same ? 0.f : (ai - frac);
        g_pack[i] = make_int4(idx, __float_as_int(m), __float_as_int(c), 0);

        if (i == 0) g_rowstart[0] = 0;
        else if (!same) g_rowstart[idx] = i;
        if (i == N - 1) last_idx = idx;
    }
    __syncthreads();

    __shared__ int s_last;
    if (tid == ((N - 1) & 1023)) s_last = last_idx;
    __syncthreads();
    for (int j = s_last + 1 + tid; j <= N + 1; j += 1024)
        g_rowstart[j] = N;
}

// ---------------------------------------------------------------------------
// Kernel 3: gather. One block per output row j; span [rowstart[j],
// rowstart[j+2]). Pack entries for the span are loaded lane-parallel and
// broadcast via shfl, so x-row loads pipeline instead of chaining.
// ---------------------------------------------------------------------------
__global__ void __launch_bounds__(256) k_gather(const float* __restrict__ x,
                                                float* __restrict__ out) {
    const int j = blockIdx.x;     // output row
    const int t = threadIdx.x;    // 0..255, float4 lanes
    const int lane = t & 31;

    const int s = __ldg(&g_rowstart[j]);
    const int e = __ldg(&g_rowstart[j + 2]);

    float4 acc = make_float4(0.f, 0.f, 0.f, 0.f);
    for (int base = s; base < e; base += 32) {
        // lane-parallel weight computation for up to 32 span columns
        float wl = 0.f;
        const int i = base + lane;
        if (i < e) {
            const int4 p = __ldg(&g_pack[i]);
            if (p.x == j)          wl = __int_as_float(p.y);   // m
            else if (p.x == j + 1) wl = __int_as_float(p.z);   // c
        }
        const int cnt = min(32, e - base);
#pragma unroll 4
        for (int k = 0; k < cnt; k++) {
            const float wk = __shfl_sync(0xffffffffu, wl, k);
            if (wk != 0.f) {   // uniform across block's warps
                const float4 v =
                    reinterpret_cast<const float4*>(x)[(size_t)(base + k) * (D / 4) + t];
                acc.x += wk * v.x;
                acc.y += wk * v.y;
                acc.z += wk * v.z;
                acc.w += wk * v.w;
            }
        }
    }
    reinterpret_cast<float4*>(out)[(size_t)j * (D / 4) + t] = acc;
}

// ---------------------------------------------------------------------------
extern "C" void kernel_launch(void* const* d_in, const int* in_sizes, int n_in,
                              void* d_out, int out_size) {
    const float* x = (const float*)d_in[0];   // [8192, 1024] f32
    const float* w = (const float*)d_in[1];   // [1024, 1]    f32
    float* out = (float*)d_out;               // [8192, 1024] f32

    k_logits<<<N / 8, 256>>>(x, w);
    k_scan<<<1, 1024>>>();
    k_gather<<<N, 256>>>(x, out);
}

// round 6
// speedup vs baseline: 1.5556x; 1.0694x over previous
#include <cuda_runtime.h>
#include <math.h>

#define N 8192
#define D 1024

// Scratch (allocation-free rule: __device__ globals)
__device__ float g_a[N];            // sigmoid(x @ w)
__device__ int4  g_pack[N];         // {idx, bits(m), bits(c), 0} per column
__device__ int   g_rowstart[N + 2]; // lower_bound(idx >= j), j in [0, N+1]

// ---------------------------------------------------------------------------
// Kernel 1: z = x @ w, a = sigmoid(z).  One warp per row. All 8 float4 row
// loads are front-batched into registers (MLP 2 -> 8), then the FFMA chain
// runs in the EXACT same order on the same values as the validated kernel
// -> g_a bitwise unchanged.
// ---------------------------------------------------------------------------
__global__ void __launch_bounds__(256) k_logits(const float* __restrict__ x,
                                                const float* __restrict__ w) {
    const int warp = threadIdx.x >> 5;
    const int lane = threadIdx.x & 31;
    const int row  = blockIdx.x * 8 + warp;

    const float4* xr = reinterpret_cast<const float4*>(x) + (size_t)row * (D / 4);
    const float4* w4 = reinterpret_cast<const float4*>(w);

    // batched independent loads — 8 LDG.128 in flight per thread
    float4 xv[8];
#pragma unroll
    for (int k = 0; k < 8; k++)
        xv[k] = xr[lane + 32 * k];

    float s = 0.f;
#pragma unroll
    for (int k = 0; k < 8; k++) {
        const float4 wv = __ldg(&w4[lane + 32 * k]);
        s += xv[k].x * wv.x;
        s += xv[k].y * wv.y;
        s += xv[k].z * wv.z;
        s += xv[k].w * wv.w;
    }
#pragma unroll
    for (int off = 16; off; off >>= 1)
        s += __shfl_xor_sync(0xffffffffu, s, off);

    if (lane == 0) {
        float z = s, a;
        if (z >= 0.f) {
            a = 1.f / (1.f + expf(-z));
        } else {
            float e = expf(z);
            a = e / (1.f + e);
        }
        g_a[row] = a;
    }
}

// ---------------------------------------------------------------------------
// Kernel 2: b = cumsum(a) replicating jax.lax.associative_scan's fp32 tree,
// then derive per-column {idx, m, c} and the exact rowstart table.
// idx is non-decreasing with steps <= 1 (a_i < 1): crossing thread writes
// rowstart directly, no atomics, no search.
// ---------------------------------------------------------------------------
__global__ void k_scan() {
    __shared__ float sh[8192];
    const int tid = threadIdx.x;   // 1024 threads

    for (int i = tid; i < 4096; i += 1024)
        sh[i] = g_a[2 * i] + g_a[2 * i + 1];
    __syncthreads();
    for (int l = 2; l <= 7; l++) {                 // n = 2048 .. 64
        const int n    = N >> l;
        const int off  = 8192 - 2 * (8192 >> l);
        const int offp = 8192 - 2 * (8192 >> (l - 1));
        for (int i = tid; i < n; i += 1024)
            sh[off + i] = sh[offp + 2 * i] + sh[offp + 2 * i + 1];
        __syncthreads();
    }

    if (tid < 32) {
        for (int l = 8; l <= 13; l++) {
            const int n    = N >> l;
            const int off  = 8192 - 2 * (8192 >> l);
            const int offp = 8192 - 2 * (8192 >> (l - 1));
            if (tid < n)
                sh[off + tid] = sh[offp + 2 * tid] + sh[offp + 2 * tid + 1];
            __syncwarp();
        }
        for (int l = 12; l >= 8; l--) {
            const int n    = N >> l;
            const int off  = 8192 - 2 * (8192 >> l);
            const int offc = 8192 - 2 * (8192 >> (l + 1));
            float v = 0.f;
            if (tid < n) {
                if (tid & 1)       v = sh[offc + (tid >> 1)];
                else if (tid == 0) v = sh[off];
                else               v = sh[offc + (tid >> 1) - 1] + sh[off + tid];
            }
            __syncwarp();
            if (tid < n) sh[off + tid] = v;
            __syncwarp();
        }
    }
    __syncthreads();

    for (int l = 7; l >= 1; l--) {                 // n = 64 .. 4096, in place
        const int n    = N >> l;
        const int off  = 8192 - 2 * (8192 >> l);
        const int offc = 8192 - 2 * (8192 >> (l + 1));
        for (int i = tid; i < n; i += 1024) {
            float v;
            if (i & 1)       v = sh[offc + (i >> 1)];
            else if (i == 0) v = sh[off];
            else             v = sh[offc + (i >> 1) - 1] + sh[off + i];
            sh[off + i] = v;
        }
        __syncthreads();
    }

    int last_idx = 0;
    for (int i = tid; i < N; i += 1024) {
        const float ai = g_a[i];
        float bi;
        if (i == 0)      bi = ai;
        else if (i & 1)  bi = sh[i >> 1];
        else             bi = sh[(i >> 1) - 1] + ai;

        int prev;
        if (i == 0) {
            prev = 0;
        } else {
            const int k = i - 1;
            float bp;
            if (k == 0)      bp = g_a[0];
            else if (k & 1)  bp = sh[k >> 1];
            else             bp = sh[(k >> 1) - 1] + g_a[k];
            prev = (int)floorf(bp);
        }
        const int idx   = (int)floorf(bi);
        const bool same = (idx == prev);
        const float frac = bi - (float)idx;

        const float m = same ? ai : frac;
        const float c = same ? 0.f : (ai - frac);
        g_pack[i] = make_int4(idx, __float_as_int(m), __float_as_int(c), 0);

        if (i == 0) g_rowstart[0] = 0;
        else if (!same) g_rowstart[idx] = i;
        if (i == N - 1) last_idx = idx;
    }
    __syncthreads();

    __shared__ int s_last;
    if (tid == ((N - 1) & 1023)) s_last = last_idx;
    __syncthreads();
    for (int j = s_last + 1 + tid; j <= N + 1; j += 1024)
        g_rowstart[j] = N;
}

// ---------------------------------------------------------------------------
// Kernel 3: gather. One block per output row j; span [rowstart[j],
// rowstart[j+2]). Pack entries for the span are loaded lane-parallel and
// broadcast via shfl, so x-row loads pipeline instead of chaining.
// ---------------------------------------------------------------------------
__global__ void __launch_bounds__(256) k_gather(const float* __restrict__ x,
                                                float* __restrict__ out) {
    const int j = blockIdx.x;     // output row
    const int t = threadIdx.x;    // 0..255, float4 lanes
    const int lane = t & 31;

    const int s = __ldg(&g_rowstart[j]);
    const int e = __ldg(&g_rowstart[j + 2]);

    float4 acc = make_float4(0.f, 0.f, 0.f, 0.f);
    for (int base = s; base < e; base += 32) {
        // lane-parallel weight computation for up to 32 span columns
        float wl = 0.f;
        const int i = base + lane;
        if (i < e) {
            const int4 p = __ldg(&g_pack[i]);
            if (p.x == j)          wl = __int_as_float(p.y);   // m
            else if (p.x == j + 1) wl = __int_as_float(p.z);   // c
        }
        const int cnt = min(32, e - base);
#pragma unroll 4
        for (int k = 0; k < cnt; k++) {
            const float wk = __shfl_sync(0xffffffffu, wl, k);
            if (wk != 0.f) {   // uniform across block's warps
                const float4 v =
                    reinterpret_cast<const float4*>(x)[(size_t)(base + k) * (D / 4) + t];
                acc.x += wk * v.x;
                acc.y += wk * v.y;
                acc.z += wk * v.z;
                acc.w += wk * v.w;
            }
        }
    }
    reinterpret_cast<float4*>(out)[(size_t)j * (D / 4) + t] = acc;
}

// ---------------------------------------------------------------------------
extern "C" void kernel_launch(void* const* d_in, const int* in_sizes, int n_in,
                              void* d_out, int out_size) {
    const float* x = (const float*)d_in[0];   // [8192, 1024] f32
    const float* w = (const float*)d_in[1];   // [1024, 1]    f32
    float* out = (float*)d_out;               // [8192, 1024] f32

    k_logits<<<N / 8, 256>>>(x, w);
    k_scan<<<1, 1024>>>();
    k_gather<<<N, 256>>>(x, out);
}